// round 2
// baseline (speedup 1.0000x reference)
#include <cuda_runtime.h>

// ---------------------------------------------------------------------------
// GQNN: 2-layer SAGEConv (mean aggr) + fc head.
//   h0 = [x | tau]                        (65 feats; tau handled separately)
//   h1 = relu(mean_aggr(h0) @ W1l + b1l + h0 @ W1r)
//   h2 = relu(mean_aggr(h1) @ W2l + b2l + h1 @ W2r)
//   out = h2 @ Wfc + bfc
// N = 100000, E = 3200000, HID = 64.
// ---------------------------------------------------------------------------

#define NMAX 100000
#define EMAX 3200000

__device__ float g_agg[NMAX * 64];   // feature aggregation buffer (reused both layers)
__device__ float g_aggT[NMAX];       // tau aggregation (layer 1 only)
__device__ float g_deg[NMAX];        // in-degree (computed once, reused)
__device__ float g_h1[NMAX * 64];    // layer-1 output
__device__ int   g_src[EMAX];
__device__ int   g_dst[EMAX];
__device__ int   g_is64;

// --- edge-index dtype detection (int64 vs int32, JAX x64-flag dependent) ----
__global__ void detect_kernel(const void* ei) {
    const long long* q = (const long long*)ei;
    int is64 = 1;
    for (int i = 0; i < 128; i++) {
        long long v = q[i];
        if (v < 0 || v >= NMAX) { is64 = 0; break; }
    }
    g_is64 = is64;
}

__global__ void convert_kernel(const void* ei, int E) {
    int i = blockIdx.x * blockDim.x + threadIdx.x;
    if (i >= E) return;
    if (g_is64) {
        const long long* q = (const long long*)ei;
        g_src[i] = (int)q[i];
        g_dst[i] = (int)q[(size_t)E + i];
    } else {
        const int* q = (const int*)ei;
        g_src[i] = q[i];
        g_dst[i] = q[E + i];
    }
}

// --- zero the aggregation buffers ------------------------------------------
__global__ void zero_kernel(int N, int zero_extra) {
    int i = blockIdx.x * blockDim.x + threadIdx.x;
    int total4 = N * 16;  // N*64 floats as float4
    if (i < total4) ((float4*)g_agg)[i] = make_float4(0.f, 0.f, 0.f, 0.f);
    if (zero_extra && i < N) { g_aggT[i] = 0.f; g_deg[i] = 0.f; }
}

// --- tau + degree scatter (once) -------------------------------------------
__global__ void scatter_td_kernel(const float* __restrict__ tau, int E) {
    int e = blockIdx.x * blockDim.x + threadIdx.x;
    if (e >= E) return;
    int s = g_src[e];
    int d = g_dst[e];
    float tv = __ldg(tau + s);
    float one = 1.0f;
    asm volatile("red.global.add.f32 [%0], %1;" :: "l"(&g_aggT[d]), "f"(tv)  : "memory");
    asm volatile("red.global.add.f32 [%0], %1;" :: "l"(&g_deg[d]),  "f"(one) : "memory");
}

// --- 64-float feature scatter: 16 threads per edge, float4 chunks ----------
// Lanes 0-15 of a warp handle one edge (contiguous 256B gather + 256B RED),
// lanes 16-31 the next edge. red.global.add.v4.f32 = 4x fewer L2 atomic ops.
__global__ void scatter_feat_kernel(const float* __restrict__ featExt, int useH1, int E) {
    long long t = (long long)blockIdx.x * blockDim.x + threadIdx.x;
    if (t >= (long long)E * 16) return;
    int e = (int)(t >> 4);
    int c = (int)(t & 15);
    const float* feat = useH1 ? g_h1 : featExt;
    int s = g_src[e];
    int d = g_dst[e];
    float4 v = __ldg((const float4*)(feat + (size_t)s * 64) + c);
    float* p = g_agg + (size_t)d * 64 + c * 4;
    asm volatile("red.global.add.v4.f32 [%0], {%1, %2, %3, %4};"
                 :: "l"(p), "f"(v.x), "f"(v.y), "f"(v.z), "f"(v.w) : "memory");
}

// --- layer 1 node update: h1 = relu(mean@W1l + b1l + h0@W1r) ---------------
__global__ void node1_kernel(const float* __restrict__ x, const float* __restrict__ tau,
                             const float* __restrict__ W1l, const float* __restrict__ b1l,
                             const float* __restrict__ W1r, int N) {
    __shared__ float sWl[65 * 64];
    __shared__ float sWr[65 * 64];
    __shared__ float sb[64];
    for (int i = threadIdx.x; i < 65 * 64; i += blockDim.x) { sWl[i] = W1l[i]; sWr[i] = W1r[i]; }
    for (int i = threadIdx.x; i < 64; i += blockDim.x) sb[i] = b1l[i];
    __syncthreads();

    int n = blockIdx.x * blockDim.x + threadIdx.x;
    if (n >= N) return;

    float inv = 1.0f / fmaxf(g_deg[n], 1.0f);
    float acc[64];
#pragma unroll
    for (int o = 0; o < 64; o++) acc[o] = sb[o];

    const float* aggRow = g_agg + (size_t)n * 64;
    const float* xRow   = x + (size_t)n * 64;

#pragma unroll 4
    for (int k = 0; k < 64; k++) {
        float am = aggRow[k] * inv;
        float ax = xRow[k];
        const float4* wl4 = (const float4*)(sWl + k * 64);
        const float4* wr4 = (const float4*)(sWr + k * 64);
#pragma unroll
        for (int o = 0; o < 16; o++) {
            float4 wl = wl4[o], wr = wr4[o];
            acc[4 * o + 0] += am * wl.x + ax * wr.x;
            acc[4 * o + 1] += am * wl.y + ax * wr.y;
            acc[4 * o + 2] += am * wl.z + ax * wr.z;
            acc[4 * o + 3] += am * wl.w + ax * wr.w;
        }
    }
    {   // augmented tau row (k = 64)
        float am = g_aggT[n] * inv;
        float ax = tau[n];
        const float4* wl4 = (const float4*)(sWl + 64 * 64);
        const float4* wr4 = (const float4*)(sWr + 64 * 64);
#pragma unroll
        for (int o = 0; o < 16; o++) {
            float4 wl = wl4[o], wr = wr4[o];
            acc[4 * o + 0] += am * wl.x + ax * wr.x;
            acc[4 * o + 1] += am * wl.y + ax * wr.y;
            acc[4 * o + 2] += am * wl.z + ax * wr.z;
            acc[4 * o + 3] += am * wl.w + ax * wr.w;
        }
    }

    float4* outRow = (float4*)(g_h1 + (size_t)n * 64);
#pragma unroll
    for (int o = 0; o < 16; o++) {
        float4 v;
        v.x = fmaxf(acc[4 * o + 0], 0.f);
        v.y = fmaxf(acc[4 * o + 1], 0.f);
        v.z = fmaxf(acc[4 * o + 2], 0.f);
        v.w = fmaxf(acc[4 * o + 3], 0.f);
        outRow[o] = v;
    }
}

// --- layer 2 node update + fused fc head -----------------------------------
__global__ void node2_kernel(const float* __restrict__ W2l, const float* __restrict__ b2l,
                             const float* __restrict__ W2r, const float* __restrict__ Wfc,
                             const float* __restrict__ bfc, float* __restrict__ out, int N) {
    __shared__ float sWl[64 * 64];
    __shared__ float sWr[64 * 64];
    __shared__ float sb[64];
    __shared__ float sfc[64];
    for (int i = threadIdx.x; i < 64 * 64; i += blockDim.x) { sWl[i] = W2l[i]; sWr[i] = W2r[i]; }
    for (int i = threadIdx.x; i < 64; i += blockDim.x) { sb[i] = b2l[i]; sfc[i] = Wfc[i]; }
    __syncthreads();

    int n = blockIdx.x * blockDim.x + threadIdx.x;
    if (n >= N) return;

    float inv = 1.0f / fmaxf(g_deg[n], 1.0f);
    float acc[64];
#pragma unroll
    for (int o = 0; o < 64; o++) acc[o] = sb[o];

    const float* aggRow = g_agg + (size_t)n * 64;
    const float* hRow   = g_h1 + (size_t)n * 64;

#pragma unroll 4
    for (int k = 0; k < 64; k++) {
        float am = aggRow[k] * inv;
        float ax = hRow[k];
        const float4* wl4 = (const float4*)(sWl + k * 64);
        const float4* wr4 = (const float4*)(sWr + k * 64);
#pragma unroll
        for (int o = 0; o < 16; o++) {
            float4 wl = wl4[o], wr = wr4[o];
            acc[4 * o + 0] += am * wl.x + ax * wr.x;
            acc[4 * o + 1] += am * wl.y + ax * wr.y;
            acc[4 * o + 2] += am * wl.z + ax * wr.z;
            acc[4 * o + 3] += am * wl.w + ax * wr.w;
        }
    }

    float r = __ldg(bfc);
#pragma unroll
    for (int o = 0; o < 64; o++) r += fmaxf(acc[o], 0.f) * sfc[o];
    out[n] = r;
}

// ---------------------------------------------------------------------------
extern "C" void kernel_launch(void* const* d_in, const int* in_sizes, int n_in,
                              void* d_out, int out_size) {
    const float* x   = (const float*)d_in[0];
    const void*  ei  = d_in[1];
    const float* tau = (const float*)d_in[2];
    const float* W1l = (const float*)d_in[3];
    const float* b1l = (const float*)d_in[4];
    const float* W1r = (const float*)d_in[5];
    const float* W2l = (const float*)d_in[6];
    const float* b2l = (const float*)d_in[7];
    const float* W2r = (const float*)d_in[8];
    const float* Wfc = (const float*)d_in[9];
    const float* bfc = (const float*)d_in[10];

    int N = in_sizes[0] / 64;
    int E = in_sizes[1] / 2;
    long long chunkTot = (long long)E * 16;
    int chunkBlocks = (int)((chunkTot + 255) / 256);

    // one-time per launch: edge index conversion + degree
    detect_kernel<<<1, 1>>>(ei);
    convert_kernel<<<(E + 255) / 256, 256>>>(ei, E);

    // ---- layer 1 ----
    zero_kernel<<<(N * 16 + 255) / 256, 256>>>(N, 1);
    scatter_td_kernel<<<(E + 255) / 256, 256>>>(tau, E);
    scatter_feat_kernel<<<chunkBlocks, 256>>>(x, 0, E);
    node1_kernel<<<(N + 127) / 128, 128>>>(x, tau, W1l, b1l, W1r, N);

    // ---- layer 2 (+ fused fc) ----
    zero_kernel<<<(N * 16 + 255) / 256, 256>>>(N, 0);
    scatter_feat_kernel<<<chunkBlocks, 256>>>(x, 1, E);
    node2_kernel<<<(N + 127) / 128, 128>>>(W2l, b2l, W2r, Wfc, bfc, (float*)d_out, N);
}

// round 7
// speedup vs baseline: 1.4937x; 1.4937x over previous
#include <cuda_runtime.h>

// ---------------------------------------------------------------------------
// GQNN: 2-layer SAGEConv (mean aggr) + fc head, CSR-gather formulation.
//   Per launch: build CSR (count/scan/bin), then per layer:
//     mean = CSR-gather of neighbor rows (no atomics on features)
//     h    = relu(mean @ Wl + b + h_prev @ Wr)   [f32x2 packed FMA]
// N = 100000, E = 3200000, HID = 64.
// ---------------------------------------------------------------------------

#define NMAX 100000
#define EMAX 3200000
#define SCAN_B 1024
#define NBLK ((NMAX + SCAN_B - 1) / SCAN_B)   // 98

__device__ float g_agg[NMAX * 64];   // neighbor MEAN (already deg-normalized)
__device__ float g_aggT[NMAX];       // tau mean (layer 1 only)
__device__ float g_h1[NMAX * 64];    // layer-1 output
__device__ int   g_esrc[EMAX];
__device__ int   g_edst[EMAX];
__device__ int   g_csr[EMAX];        // src indices binned by dst
__device__ int   g_cnt[NMAX];
__device__ int   g_part[NMAX];       // per-block exclusive scan partials
__device__ int   g_off[NMAX + 1];
__device__ int   g_cursor[NMAX];
__device__ int   g_bsum[NBLK];
__device__ int   g_bpre[NBLK];
__device__ int   g_is64;

// --- edge-index dtype detection (int64 vs int32) ----------------------------
__global__ void detect_kernel(const void* ei) {
    const long long* q = (const long long*)ei;
    int is64 = 1;
    for (int i = 0; i < 128; i++) {
        long long v = q[i];
        if (v < 0 || v >= NMAX) { is64 = 0; break; }
    }
    g_is64 = is64;
}

__global__ void zero_cnt_kernel(int N) {
    int i = blockIdx.x * blockDim.x + threadIdx.x;
    if (i < N) g_cnt[i] = 0;
}

// --- convert edges to int32 + histogram dst degrees -------------------------
__global__ void convert_hist_kernel(const void* ei, int E) {
    int i = blockIdx.x * blockDim.x + threadIdx.x;
    if (i >= E) return;
    int s, d;
    if (g_is64) {
        const long long* q = (const long long*)ei;
        s = (int)q[i];
        d = (int)q[(size_t)E + i];
    } else {
        const int* q = (const int*)ei;
        s = q[i];
        d = q[E + i];
    }
    g_esrc[i] = s;
    g_edst[i] = d;
    atomicAdd(&g_cnt[d], 1);
}

// --- 3-kernel exclusive scan of g_cnt --------------------------------------
__global__ void scan1_kernel(int N) {
    __shared__ int sm[SCAN_B];
    int i = blockIdx.x * SCAN_B + threadIdx.x;
    int v = (i < N) ? g_cnt[i] : 0;
    sm[threadIdx.x] = v;
    __syncthreads();
    for (int off = 1; off < SCAN_B; off <<= 1) {
        int t = (threadIdx.x >= off) ? sm[threadIdx.x - off] : 0;
        __syncthreads();
        sm[threadIdx.x] += t;
        __syncthreads();
    }
    if (i < N) g_part[i] = sm[threadIdx.x] - v;  // exclusive within block
    if (threadIdx.x == SCAN_B - 1) g_bsum[blockIdx.x] = sm[SCAN_B - 1];
}

__global__ void scan2_kernel(int nb, int N, int E) {
    __shared__ int sm[128];
    int v = (threadIdx.x < nb) ? g_bsum[threadIdx.x] : 0;
    sm[threadIdx.x] = v;
    __syncthreads();
    for (int off = 1; off < 128; off <<= 1) {
        int t = (threadIdx.x >= off) ? sm[threadIdx.x - off] : 0;
        __syncthreads();
        sm[threadIdx.x] += t;
        __syncthreads();
    }
    if (threadIdx.x < nb) g_bpre[threadIdx.x] = sm[threadIdx.x] - v;
    if (threadIdx.x == 0) g_off[N] = E;
}

__global__ void scan3_kernel(int N) {
    int i = blockIdx.x * SCAN_B + threadIdx.x;
    if (i < N) {
        int o = g_part[i] + g_bpre[blockIdx.x];
        g_off[i] = o;
        g_cursor[i] = o;
    }
}

// --- bin edges into CSR -----------------------------------------------------
__global__ void build_kernel(int E) {
    int e = blockIdx.x * blockDim.x + threadIdx.x;
    if (e >= E) return;
    int d = g_edst[e];
    int pos = atomicAdd(&g_cursor[d], 1);
    g_csr[pos] = g_esrc[e];
}

// --- CSR gather aggregation: 16 threads/node, float4 lanes ------------------
// Writes the MEAN directly (deg-normalized). Layer 1 also aggregates tau.
__global__ void aggregate_kernel(const float* __restrict__ featExt,
                                 const float* __restrict__ tau,
                                 int useH1, int layer1, int N) {
    int t = blockIdx.x * blockDim.x + threadIdx.x;
    int n = t >> 4;
    int c = t & 15;
    if (n >= N) return;
    const float* feat = useH1 ? g_h1 : featExt;

    int beg = g_off[n];
    int end = g_off[n + 1];
    float4 a = make_float4(0.f, 0.f, 0.f, 0.f);
    float ts = 0.f;

    int i = beg;
    for (; i + 2 <= end; i += 2) {
        int s0 = __ldg(g_csr + i);
        int s1 = __ldg(g_csr + i + 1);
        float4 v0 = __ldg((const float4*)(feat + (size_t)s0 * 64) + c);
        float4 v1 = __ldg((const float4*)(feat + (size_t)s1 * 64) + c);
        a.x += v0.x + v1.x; a.y += v0.y + v1.y;
        a.z += v0.z + v1.z; a.w += v0.w + v1.w;
        if (layer1 && c == 0) ts += __ldg(tau + s0) + __ldg(tau + s1);
    }
    if (i < end) {
        int s0 = __ldg(g_csr + i);
        float4 v0 = __ldg((const float4*)(feat + (size_t)s0 * 64) + c);
        a.x += v0.x; a.y += v0.y; a.z += v0.z; a.w += v0.w;
        if (layer1 && c == 0) ts += __ldg(tau + s0);
    }

    float inv = 1.0f / fmaxf((float)(end - beg), 1.0f);
    a.x *= inv; a.y *= inv; a.z *= inv; a.w *= inv;
    ((float4*)g_agg)[(size_t)n * 16 + c] = a;
    if (layer1 && c == 0) g_aggT[n] = ts * inv;
}

// --- packed f32x2 FMA helpers ----------------------------------------------
__device__ __forceinline__ unsigned long long pack2(float v) {
    unsigned long long r;
    asm("mov.b64 %0, {%1, %1};" : "=l"(r) : "r"(__float_as_uint(v)));
    return r;
}
__device__ __forceinline__ void ffma2(unsigned long long& d,
                                      unsigned long long a, unsigned long long b) {
    asm("fma.rn.f32x2 %0, %1, %2, %0;" : "+l"(d) : "l"(a), "l"(b));
}
__device__ __forceinline__ void unpack2(unsigned long long v, float& lo, float& hi) {
    unsigned int a, b;
    asm("mov.b64 {%0, %1}, %2;" : "=r"(a), "=r"(b) : "l"(v));
    lo = __uint_as_float(a); hi = __uint_as_float(b);
}
__device__ __forceinline__ unsigned long long packab(float a, float b) {
    unsigned long long r;
    asm("mov.b64 %0, {%1, %2};" : "=l"(r) : "r"(__float_as_uint(a)), "r"(__float_as_uint(b)));
    return r;
}

// --- layer 1 node update: h1 = relu(mean@W1l + b1l + [x|tau]@W1r) ----------
__global__ void node1_kernel(const float* __restrict__ x, const float* __restrict__ tau,
                             const float* __restrict__ W1l, const float* __restrict__ b1l,
                             const float* __restrict__ W1r, int N) {
    __shared__ __align__(16) float sWl[65 * 64];
    __shared__ __align__(16) float sWr[65 * 64];
    __shared__ float sb[64];
    for (int i = threadIdx.x; i < 65 * 64; i += blockDim.x) { sWl[i] = W1l[i]; sWr[i] = W1r[i]; }
    for (int i = threadIdx.x; i < 64; i += blockDim.x) sb[i] = b1l[i];
    __syncthreads();

    int n = blockIdx.x * blockDim.x + threadIdx.x;
    if (n >= N) return;

    unsigned long long acc[32];
#pragma unroll
    for (int o = 0; o < 32; o++) acc[o] = packab(sb[2 * o], sb[2 * o + 1]);

    const float* aggRow = g_agg + (size_t)n * 64;  // already mean
    const float* xRow   = x + (size_t)n * 64;

#pragma unroll 4
    for (int k = 0; k < 65; k++) {
        float am = (k < 64) ? aggRow[k] : g_aggT[n];
        float ax = (k < 64) ? xRow[k]   : tau[n];
        unsigned long long am2 = pack2(am);
        unsigned long long ax2 = pack2(ax);
        const ulonglong2* wl = (const ulonglong2*)(sWl + k * 64);
        const ulonglong2* wr = (const ulonglong2*)(sWr + k * 64);
#pragma unroll
        for (int o = 0; o < 16; o++) {
            ulonglong2 l = wl[o];
            ulonglong2 r = wr[o];
            ffma2(acc[2 * o + 0], am2, l.x);
            ffma2(acc[2 * o + 0], ax2, r.x);
            ffma2(acc[2 * o + 1], am2, l.y);
            ffma2(acc[2 * o + 1], ax2, r.y);
        }
    }

    float4* outRow = (float4*)(g_h1 + (size_t)n * 64);
#pragma unroll
    for (int o = 0; o < 16; o++) {
        float a0, a1, a2, a3;
        unpack2(acc[2 * o + 0], a0, a1);
        unpack2(acc[2 * o + 1], a2, a3);
        float4 v;
        v.x = fmaxf(a0, 0.f); v.y = fmaxf(a1, 0.f);
        v.z = fmaxf(a2, 0.f); v.w = fmaxf(a3, 0.f);
        outRow[o] = v;
    }
}

// --- layer 2 node update + fused fc head -----------------------------------
__global__ void node2_kernel(const float* __restrict__ W2l, const float* __restrict__ b2l,
                             const float* __restrict__ W2r, const float* __restrict__ Wfc,
                             const float* __restrict__ bfc, float* __restrict__ out, int N) {
    __shared__ __align__(16) float sWl[64 * 64];
    __shared__ __align__(16) float sWr[64 * 64];
    __shared__ float sb[64];
    __shared__ float sfc[64];
    for (int i = threadIdx.x; i < 64 * 64; i += blockDim.x) { sWl[i] = W2l[i]; sWr[i] = W2r[i]; }
    for (int i = threadIdx.x; i < 64; i += blockDim.x) { sb[i] = b2l[i]; sfc[i] = Wfc[i]; }
    __syncthreads();

    int n = blockIdx.x * blockDim.x + threadIdx.x;
    if (n >= N) return;

    unsigned long long acc[32];
#pragma unroll
    for (int o = 0; o < 32; o++) acc[o] = packab(sb[2 * o], sb[2 * o + 1]);

    const float* aggRow = g_agg + (size_t)n * 64;  // already mean
    const float* hRow   = g_h1 + (size_t)n * 64;

#pragma unroll 4
    for (int k = 0; k < 64; k++) {
        unsigned long long am2 = pack2(aggRow[k]);
        unsigned long long ax2 = pack2(hRow[k]);
        const ulonglong2* wl = (const ulonglong2*)(sWl + k * 64);
        const ulonglong2* wr = (const ulonglong2*)(sWr + k * 64);
#pragma unroll
        for (int o = 0; o < 16; o++) {
            ulonglong2 l = wl[o];
            ulonglong2 r = wr[o];
            ffma2(acc[2 * o + 0], am2, l.x);
            ffma2(acc[2 * o + 0], ax2, r.x);
            ffma2(acc[2 * o + 1], am2, l.y);
            ffma2(acc[2 * o + 1], ax2, r.y);
        }
    }

    float r = __ldg(bfc);
#pragma unroll
    for (int o = 0; o < 32; o++) {
        float a0, a1;
        unpack2(acc[o], a0, a1);
        r += fmaxf(a0, 0.f) * sfc[2 * o] + fmaxf(a1, 0.f) * sfc[2 * o + 1];
    }
    out[n] = r;
}

// ---------------------------------------------------------------------------
extern "C" void kernel_launch(void* const* d_in, const int* in_sizes, int n_in,
                              void* d_out, int out_size) {
    const float* x   = (const float*)d_in[0];
    const void*  ei  = d_in[1];
    const float* tau = (const float*)d_in[2];
    const float* W1l = (const float*)d_in[3];
    const float* b1l = (const float*)d_in[4];
    const float* W1r = (const float*)d_in[5];
    const float* W2l = (const float*)d_in[6];
    const float* b2l = (const float*)d_in[7];
    const float* W2r = (const float*)d_in[8];
    const float* Wfc = (const float*)d_in[9];
    const float* bfc = (const float*)d_in[10];

    int N = in_sizes[0] / 64;
    int E = in_sizes[1] / 2;
    int nb = (N + SCAN_B - 1) / SCAN_B;
    int eb = (E + 255) / 256;
    int ab = (N * 16 + 255) / 256;

    // ---- CSR build (once per launch) ----
    detect_kernel<<<1, 1>>>(ei);
    zero_cnt_kernel<<<(N + 255) / 256, 256>>>(N);
    convert_hist_kernel<<<eb, 256>>>(ei, E);
    scan1_kernel<<<nb, SCAN_B>>>(N);
    scan2_kernel<<<1, 128>>>(nb, N, E);
    scan3_kernel<<<nb, SCAN_B>>>(N);
    build_kernel<<<eb, 256>>>(E);

    // ---- layer 1 ----
    aggregate_kernel<<<ab, 256>>>(x, tau, 0, 1, N);
    node1_kernel<<<(N + 127) / 128, 128>>>(x, tau, W1l, b1l, W1r, N);

    // ---- layer 2 (+ fused fc) ----
    aggregate_kernel<<<ab, 256>>>(x, tau, 1, 0, N);
    node2_kernel<<<(N + 127) / 128, 128>>>(W2l, b2l, W2r, Wfc, bfc, (float*)d_out, N);
}

// round 15
// speedup vs baseline: 1.6875x; 1.1297x over previous
#include <cuda_runtime.h>
#include <cuda_fp16.h>

// ---------------------------------------------------------------------------
// GQNN: 2-layer SAGEConv (mean aggr) + fc head, CSR-gather formulation.
//   CSR build once per launch; per layer:
//     mean = CSR gather of fp16 neighbor rows (fp32 accumulate, no atomics)
//     h    = relu(mean @ Wl + b + h_prev @ Wr)   [f32x2 packed FMA]
// N = 100000, E = 3200000, HID = 64.
// NOTE: __device__ global buffers are selected INSIDE device code (flag arg);
// passing a __device__ symbol as a kernel argument from host is invalid.
// ---------------------------------------------------------------------------

#define NMAX 100000
#define EMAX 3200000
#define SCAN_B 1024
#define NBLK ((NMAX + SCAN_B - 1) / SCAN_B)   // 98

__device__ __align__(16) float  g_agg[NMAX * 64];   // neighbor MEAN (deg-normalized, fp32)
__device__ float  g_aggT[NMAX];                     // tau mean (layer 1 only)
__device__ __align__(16) float  g_h1[NMAX * 64];    // layer-1 output (fp32, self term)
__device__ __align__(16) __half g_xh[NMAX * 64];    // fp16 copy of x (gather source L1)
__device__ __align__(16) __half g_h1h[NMAX * 64];   // fp16 copy of h1 (gather source L2)
__device__ int    g_esrc[EMAX];
__device__ int    g_edst[EMAX];
__device__ int    g_csr[EMAX];        // src indices binned by dst
__device__ int    g_cnt[NMAX];
__device__ int    g_part[NMAX];
__device__ int    g_off[NMAX + 1];
__device__ int    g_cursor[NMAX];
__device__ int    g_bsum[NBLK];
__device__ int    g_bpre[NBLK];
__device__ int    g_is64;

// --- edge-index dtype detection (int64 vs int32) ----------------------------
__global__ void detect_kernel(const void* ei) {
    const long long* q = (const long long*)ei;
    int is64 = 1;
    for (int i = 0; i < 128; i++) {
        long long v = q[i];
        if (v < 0 || v >= NMAX) { is64 = 0; break; }
    }
    g_is64 = is64;
}

// --- fused: zero degree counters + fp16 copy of x ---------------------------
__global__ void prep_kernel(const float* __restrict__ x, int N) {
    int i = blockIdx.x * blockDim.x + threadIdx.x;   // grid covers N*16
    if (i < N) g_cnt[i] = 0;
    if (i >= N * 16) return;
    float4 v = __ldg((const float4*)x + i);
    __half2 lo = __floats2half2_rn(v.x, v.y);
    __half2 hi = __floats2half2_rn(v.z, v.w);
    uint2 o;
    o.x = *(unsigned int*)&lo;
    o.y = *(unsigned int*)&hi;
    ((uint2*)g_xh)[i] = o;
}

// --- convert edges to int32 + histogram dst degrees -------------------------
__global__ void convert_hist_kernel(const void* ei, int E) {
    int i = blockIdx.x * blockDim.x + threadIdx.x;
    if (i >= E) return;
    int s, d;
    if (g_is64) {
        const long long* q = (const long long*)ei;
        s = (int)q[i];
        d = (int)q[(size_t)E + i];
    } else {
        const int* q = (const int*)ei;
        s = q[i];
        d = q[E + i];
    }
    g_esrc[i] = s;
    g_edst[i] = d;
    atomicAdd(&g_cnt[d], 1);
}

// --- 3-kernel exclusive scan of g_cnt --------------------------------------
__global__ void scan1_kernel(int N) {
    __shared__ int sm[SCAN_B];
    int i = blockIdx.x * SCAN_B + threadIdx.x;
    int v = (i < N) ? g_cnt[i] : 0;
    sm[threadIdx.x] = v;
    __syncthreads();
    for (int off = 1; off < SCAN_B; off <<= 1) {
        int t = (threadIdx.x >= off) ? sm[threadIdx.x - off] : 0;
        __syncthreads();
        sm[threadIdx.x] += t;
        __syncthreads();
    }
    if (i < N) g_part[i] = sm[threadIdx.x] - v;
    if (threadIdx.x == SCAN_B - 1) g_bsum[blockIdx.x] = sm[SCAN_B - 1];
}

__global__ void scan2_kernel(int nb, int N, int E) {
    __shared__ int sm[128];
    int v = (threadIdx.x < nb) ? g_bsum[threadIdx.x] : 0;
    sm[threadIdx.x] = v;
    __syncthreads();
    for (int off = 1; off < 128; off <<= 1) {
        int t = (threadIdx.x >= off) ? sm[threadIdx.x - off] : 0;
        __syncthreads();
        sm[threadIdx.x] += t;
        __syncthreads();
    }
    if (threadIdx.x < nb) g_bpre[threadIdx.x] = sm[threadIdx.x] - v;
    if (threadIdx.x == 0) g_off[N] = E;
}

__global__ void scan3_kernel(int N) {
    int i = blockIdx.x * SCAN_B + threadIdx.x;
    if (i < N) {
        int o = g_part[i] + g_bpre[blockIdx.x];
        g_off[i] = o;
        g_cursor[i] = o;
    }
}

// --- bin edges into CSR -----------------------------------------------------
__global__ void build_kernel(int E) {
    int e = blockIdx.x * blockDim.x + threadIdx.x;
    if (e >= E) return;
    int d = __ldg(g_edst + e);
    int pos = atomicAdd(&g_cursor[d], 1);
    g_csr[pos] = __ldg(g_esrc + e);
}

// --- CSR gather aggregation over fp16 rows: 16 lanes/node, 8 B per lane -----
// One neighbor row = 64 halves = 128 B = exactly one L2 line per half-warp.
// fp32 accumulation; writes the deg-normalized MEAN in fp32.
// Buffer selected in DEVICE code via useH1 flag (g_xh / g_h1h are device syms).
__global__ void aggregate_kernel(const float* __restrict__ tau,
                                 int useH1, int layer1, int N) {
    int t = blockIdx.x * blockDim.x + threadIdx.x;
    int n = t >> 4;
    int c = t & 15;        // lane handles cols [4c, 4c+4)
    if (n >= N) return;
    const __half* feat16 = useH1 ? g_h1h : g_xh;

    int beg = g_off[n];
    int end = g_off[n + 1];
    float a0 = 0.f, a1 = 0.f, a2 = 0.f, a3 = 0.f;
    float ts = 0.f;

    int i = beg;
    for (; i + 4 <= end; i += 4) {
        int s0 = __ldg(g_csr + i);
        int s1 = __ldg(g_csr + i + 1);
        int s2 = __ldg(g_csr + i + 2);
        int s3 = __ldg(g_csr + i + 3);
        uint2 v0 = __ldg((const uint2*)(feat16 + (size_t)s0 * 64) + c);
        uint2 v1 = __ldg((const uint2*)(feat16 + (size_t)s1 * 64) + c);
        uint2 v2 = __ldg((const uint2*)(feat16 + (size_t)s2 * 64) + c);
        uint2 v3 = __ldg((const uint2*)(feat16 + (size_t)s3 * 64) + c);
        float2 f;
        f = __half22float2(*(__half2*)&v0.x); a0 += f.x; a1 += f.y;
        f = __half22float2(*(__half2*)&v0.y); a2 += f.x; a3 += f.y;
        f = __half22float2(*(__half2*)&v1.x); a0 += f.x; a1 += f.y;
        f = __half22float2(*(__half2*)&v1.y); a2 += f.x; a3 += f.y;
        f = __half22float2(*(__half2*)&v2.x); a0 += f.x; a1 += f.y;
        f = __half22float2(*(__half2*)&v2.y); a2 += f.x; a3 += f.y;
        f = __half22float2(*(__half2*)&v3.x); a0 += f.x; a1 += f.y;
        f = __half22float2(*(__half2*)&v3.y); a2 += f.x; a3 += f.y;
        if (layer1 && c == 0)
            ts += __ldg(tau + s0) + __ldg(tau + s1) + __ldg(tau + s2) + __ldg(tau + s3);
    }
    for (; i < end; i++) {
        int s0 = __ldg(g_csr + i);
        uint2 v0 = __ldg((const uint2*)(feat16 + (size_t)s0 * 64) + c);
        float2 f;
        f = __half22float2(*(__half2*)&v0.x); a0 += f.x; a1 += f.y;
        f = __half22float2(*(__half2*)&v0.y); a2 += f.x; a3 += f.y;
        if (layer1 && c == 0) ts += __ldg(tau + s0);
    }

    float inv = 1.0f / fmaxf((float)(end - beg), 1.0f);
    float4 o;
    o.x = a0 * inv; o.y = a1 * inv; o.z = a2 * inv; o.w = a3 * inv;
    ((float4*)g_agg)[(size_t)n * 16 + c] = o;
    if (layer1 && c == 0) g_aggT[n] = ts * inv;
}

// --- packed f32x2 FMA helpers ----------------------------------------------
__device__ __forceinline__ unsigned long long pack2(float v) {
    unsigned long long r;
    asm("mov.b64 %0, {%1, %1};" : "=l"(r) : "r"(__float_as_uint(v)));
    return r;
}
__device__ __forceinline__ void ffma2(unsigned long long& d,
                                      unsigned long long a, unsigned long long b) {
    asm("fma.rn.f32x2 %0, %1, %2, %0;" : "+l"(d) : "l"(a), "l"(b));
}
__device__ __forceinline__ void unpack2(unsigned long long v, float& lo, float& hi) {
    unsigned int a, b;
    asm("mov.b64 {%0, %1}, %2;" : "=r"(a), "=r"(b) : "l"(v));
    lo = __uint_as_float(a); hi = __uint_as_float(b);
}
__device__ __forceinline__ unsigned long long packab(float a, float b) {
    unsigned long long r;
    asm("mov.b64 %0, {%1, %2};" : "=l"(r) : "r"(__float_as_uint(a)), "r"(__float_as_uint(b)));
    return r;
}

// --- layer 1 node update: h1 = relu(mean@W1l + b1l + [x|tau]@W1r) ----------
// Also emits the fp16 copy of h1 used by the layer-2 gather.
__global__ void node1_kernel(const float* __restrict__ x, const float* __restrict__ tau,
                             const float* __restrict__ W1l, const float* __restrict__ b1l,
                             const float* __restrict__ W1r, int N) {
    __shared__ __align__(16) float sWl[65 * 64];
    __shared__ __align__(16) float sWr[65 * 64];
    __shared__ float sb[64];
    for (int i = threadIdx.x; i < 65 * 64; i += blockDim.x) { sWl[i] = W1l[i]; sWr[i] = W1r[i]; }
    for (int i = threadIdx.x; i < 64; i += blockDim.x) sb[i] = b1l[i];
    __syncthreads();

    int n = blockIdx.x * blockDim.x + threadIdx.x;
    if (n >= N) return;

    unsigned long long acc[32];
#pragma unroll
    for (int o = 0; o < 32; o++) acc[o] = packab(sb[2 * o], sb[2 * o + 1]);

    const float* aggRow = g_agg + (size_t)n * 64;  // already mean
    const float* xRow   = x + (size_t)n * 64;

#pragma unroll 4
    for (int k = 0; k < 65; k++) {
        float am = (k < 64) ? aggRow[k] : g_aggT[n];
        float ax = (k < 64) ? xRow[k]   : tau[n];
        unsigned long long am2 = pack2(am);
        unsigned long long ax2 = pack2(ax);
        const ulonglong2* wl = (const ulonglong2*)(sWl + k * 64);
        const ulonglong2* wr = (const ulonglong2*)(sWr + k * 64);
#pragma unroll
        for (int o = 0; o < 16; o++) {
            ulonglong2 l = wl[o];
            ulonglong2 r = wr[o];
            ffma2(acc[2 * o + 0], am2, l.x);
            ffma2(acc[2 * o + 0], ax2, r.x);
            ffma2(acc[2 * o + 1], am2, l.y);
            ffma2(acc[2 * o + 1], ax2, r.y);
        }
    }

    float4* outRow  = (float4*)(g_h1 + (size_t)n * 64);
    uint2*  outRowH = (uint2*)(g_h1h + (size_t)n * 64);
#pragma unroll
    for (int o = 0; o < 16; o++) {
        float a0, a1, a2, a3;
        unpack2(acc[2 * o + 0], a0, a1);
        unpack2(acc[2 * o + 1], a2, a3);
        float4 v;
        v.x = fmaxf(a0, 0.f); v.y = fmaxf(a1, 0.f);
        v.z = fmaxf(a2, 0.f); v.w = fmaxf(a3, 0.f);
        outRow[o] = v;
        __half2 lo = __floats2half2_rn(v.x, v.y);
        __half2 hi = __floats2half2_rn(v.z, v.w);
        uint2 hv;
        hv.x = *(unsigned int*)&lo;
        hv.y = *(unsigned int*)&hi;
        outRowH[o] = hv;
    }
}

// --- layer 2 node update + fused fc head -----------------------------------
__global__ void node2_kernel(const float* __restrict__ W2l, const float* __restrict__ b2l,
                             const float* __restrict__ W2r, const float* __restrict__ Wfc,
                             const float* __restrict__ bfc, float* __restrict__ out, int N) {
    __shared__ __align__(16) float sWl[64 * 64];
    __shared__ __align__(16) float sWr[64 * 64];
    __shared__ float sb[64];
    __shared__ float sfc[64];
    for (int i = threadIdx.x; i < 64 * 64; i += blockDim.x) { sWl[i] = W2l[i]; sWr[i] = W2r[i]; }
    for (int i = threadIdx.x; i < 64; i += blockDim.x) { sb[i] = b2l[i]; sfc[i] = Wfc[i]; }
    __syncthreads();

    int n = blockIdx.x * blockDim.x + threadIdx.x;
    if (n >= N) return;

    unsigned long long acc[32];
#pragma unroll
    for (int o = 0; o < 32; o++) acc[o] = packab(sb[2 * o], sb[2 * o + 1]);

    const float* aggRow = g_agg + (size_t)n * 64;  // already mean
    const float* hRow   = g_h1 + (size_t)n * 64;

#pragma unroll 4
    for (int k = 0; k < 64; k++) {
        unsigned long long am2 = pack2(aggRow[k]);
        unsigned long long ax2 = pack2(hRow[k]);
        const ulonglong2* wl = (const ulonglong2*)(sWl + k * 64);
        const ulonglong2* wr = (const ulonglong2*)(sWr + k * 64);
#pragma unroll
        for (int o = 0; o < 16; o++) {
            ulonglong2 l = wl[o];
            ulonglong2 r = wr[o];
            ffma2(acc[2 * o + 0], am2, l.x);
            ffma2(acc[2 * o + 0], ax2, r.x);
            ffma2(acc[2 * o + 1], am2, l.y);
            ffma2(acc[2 * o + 1], ax2, r.y);
        }
    }

    float r = __ldg(bfc);
#pragma unroll
    for (int o = 0; o < 32; o++) {
        float a0, a1;
        unpack2(acc[o], a0, a1);
        r += fmaxf(a0, 0.f) * sfc[2 * o] + fmaxf(a1, 0.f) * sfc[2 * o + 1];
    }
    out[n] = r;
}

// ---------------------------------------------------------------------------
extern "C" void kernel_launch(void* const* d_in, const int* in_sizes, int n_in,
                              void* d_out, int out_size) {
    const float* x   = (const float*)d_in[0];
    const void*  ei  = d_in[1];
    const float* tau = (const float*)d_in[2];
    const float* W1l = (const float*)d_in[3];
    const float* b1l = (const float*)d_in[4];
    const float* W1r = (const float*)d_in[5];
    const float* W2l = (const float*)d_in[6];
    const float* b2l = (const float*)d_in[7];
    const float* W2r = (const float*)d_in[8];
    const float* Wfc = (const float*)d_in[9];
    const float* bfc = (const float*)d_in[10];

    int N = in_sizes[0] / 64;
    int E = in_sizes[1] / 2;
    int nb = (N + SCAN_B - 1) / SCAN_B;
    int eb = (E + 255) / 256;
    int ab = (N * 16 + 255) / 256;

    // ---- CSR build (once per launch) + fp16 copy of x ----
    detect_kernel<<<1, 1>>>(ei);
    prep_kernel<<<ab, 256>>>(x, N);
    convert_hist_kernel<<<eb, 256>>>(ei, E);
    scan1_kernel<<<nb, SCAN_B>>>(N);
    scan2_kernel<<<1, 128>>>(nb, N, E);
    scan3_kernel<<<nb, SCAN_B>>>(N);
    build_kernel<<<eb, 256>>>(E);

    // ---- layer 1 ----
    aggregate_kernel<<<ab, 256>>>(tau, 0, 1, N);
    node1_kernel<<<(N + 127) / 128, 128>>>(x, tau, W1l, b1l, W1r, N);

    // ---- layer 2 (+ fused fc) ----
    aggregate_kernel<<<ab, 256>>>(tau, 1, 0, N);
    node2_kernel<<<(N + 127) / 128, 128>>>(W2l, b2l, W2r, Wfc, bfc, (float*)d_out, N);
}